// round 15
// baseline (speedup 1.0000x reference)
#include <cuda_runtime.h>
#include <cuda_fp16.h>

#define USER_NUM 100000
#define ITEM_NUM 50000
#define N_NODES  150000
#define EMB      64
#define TOT      (N_NODES * EMB)
#define TOT4     (TOT / 4)
#define NNZ_MAX  2400000
#define NSCAN_BLK ((N_NODES + 255) / 256)   /* 586 */
#define NTILE64   ((N_NODES + 63) / 64)     /* 2344 */
#define FUSED_GRID 444                      /* 148 SMs x 3 blocks */
#define FUSED_SMEM 65536                    /* 16K ws1 + 16K ws2 + 16K ssh + 16K psh */

typedef unsigned long long u64;

// ---------------- packed f32x2 helpers (FFMA2 et al., PTX-only) ------------
__device__ __forceinline__ u64 fma2(u64 a, u64 b, u64 c) {
    u64 d; asm("fma.rn.f32x2 %0, %1, %2, %3;" : "=l"(d) : "l"(a), "l"(b), "l"(c));
    return d;
}
__device__ __forceinline__ u64 add2(u64 a, u64 b) {
    u64 d; asm("add.rn.f32x2 %0, %1, %2;" : "=l"(d) : "l"(a), "l"(b));
    return d;
}
__device__ __forceinline__ u64 mul2(u64 a, u64 b) {
    u64 d; asm("mul.rn.f32x2 %0, %1, %2;" : "=l"(d) : "l"(a), "l"(b));
    return d;
}
__device__ __forceinline__ u64 dup2(float s) {
    u64 d; asm("mov.b64 %0, {%1, %1};" : "=l"(d) : "f"(s));
    return d;
}
__device__ __forceinline__ u64 pack2(float lo, float hi) {
    u64 d; asm("mov.b64 %0, {%1, %2};" : "=l"(d) : "f"(lo), "f"(hi));
    return d;
}
__device__ __forceinline__ float2 unpack2(u64 v) {
    float2 r; asm("mov.b64 {%0, %1}, %2;" : "=f"(r.x), "=f"(r.y) : "l"(v));
    return r;
}

// Scratch: fp32 egos A/B/C; fp16 shadow copies H0/H1 (gather feed, double-buffered)
__device__ float g_egoA[TOT];
__device__ float g_egoB[TOT];
__device__ float g_egoC[TOT];
__device__ uint2 g_h0[TOT4];                // 19.2MB fp16 ego (4 halves per uint2)
__device__ uint2 g_h1[TOT4];
__device__ int   g_cnt[N_NODES];
__device__ int   g_rowptr[N_NODES + 1];
__device__ int   g_cursor[N_NODES];
__device__ int   g_blksum[NSCAN_BLK];
__device__ int2  g_edge[NNZ_MAX];           // (col, val bits) packed

__device__ __forceinline__ uint2 f4_to_h4(float x, float y, float z, float w) {
    __half2 h01 = __floats2half2_rn(x, y);
    __half2 h23 = __floats2half2_rn(z, w);
    uint2 r;
    r.x = *reinterpret_cast<unsigned*>(&h01);
    r.y = *reinterpret_cast<unsigned*>(&h23);
    return r;
}

// ---------------------------------------------------------------------------
// init: egoA = concat(user,item); h0 = fp16(egoA); zero CSR histogram
// ---------------------------------------------------------------------------
__global__ void init_kernel(const float4* __restrict__ user,
                            const float4* __restrict__ item) {
    int i = blockIdx.x * blockDim.x + threadIdx.x;
    if (i < N_NODES) g_cnt[i] = 0;
    if (i >= TOT4) return;
    const int U4 = USER_NUM * EMB / 4;
    float4 v = (i < U4) ? user[i] : item[i - U4];
    reinterpret_cast<float4*>(g_egoA)[i] = v;
    g_h0[i] = f4_to_h4(v.x, v.y, v.z, v.w);
}

// ---------------------------------------------------------------------------
// CSR build: histogram -> 2-level scan -> scatter (col,val packed)
// ---------------------------------------------------------------------------
__global__ void hist_kernel(const int* __restrict__ rows, int nnz) {
    int e = blockIdx.x * blockDim.x + threadIdx.x;
    if (e < nnz) atomicAdd(&g_cnt[rows[e]], 1);
}

__global__ void scan1_kernel() {
    __shared__ int sh[256];
    int t = threadIdx.x;
    int sid = blockIdx.x * 256 + t;
    int v = (sid < N_NODES) ? g_cnt[sid] : 0;
    sh[t] = v;
    __syncthreads();
#pragma unroll
    for (int off = 1; off < 256; off <<= 1) {
        int x = (t >= off) ? sh[t - off] : 0;
        __syncthreads();
        sh[t] += x;
        __syncthreads();
    }
    if (sid < N_NODES) g_rowptr[sid] = sh[t] - v;
    if (t == 255) g_blksum[blockIdx.x] = sh[255];
}

__global__ void scan2_kernel() {
    __shared__ int sh[1024];
    int t = threadIdx.x;
    int v = (t < NSCAN_BLK) ? g_blksum[t] : 0;
    sh[t] = v;
    __syncthreads();
#pragma unroll
    for (int off = 1; off < 1024; off <<= 1) {
        int x = (t >= off) ? sh[t - off] : 0;
        __syncthreads();
        sh[t] += x;
        __syncthreads();
    }
    if (t < NSCAN_BLK) g_blksum[t] = sh[t] - v;
}

__global__ void scan3_kernel(int nnz) {
    int sid = blockIdx.x * blockDim.x + threadIdx.x;
    if (sid >= N_NODES) return;
    int rp = g_rowptr[sid] + g_blksum[sid >> 8];
    g_rowptr[sid] = rp;
    g_cursor[sid] = rp;
    if (sid == 0) g_rowptr[N_NODES] = nnz;
}

__global__ void scatter_kernel(const int* __restrict__ rows,
                               const int* __restrict__ cols,
                               const float* __restrict__ vals, int nnz) {
    int e = blockIdx.x * blockDim.x + threadIdx.x;
    if (e >= nnz) return;
    int r = rows[e];
    int pos = atomicAdd(&g_cursor[r], 1);
    g_edge[pos] = make_int2(cols[e], __float_as_int(vals[e]));
}

// ---------------------------------------------------------------------------
// CSR gather: fp16 row loads (8B/lane), fp32 convert + accumulate.
// 8-unrolled for MLP.
// ---------------------------------------------------------------------------
__device__ __forceinline__ void gather_row(const uint2* __restrict__ srcH,
                                           int row, int t, u64& a01, u64& a23) {
    int i  = g_rowptr[row];
    int e0 = g_rowptr[row + 1];
    for (; i + 7 < e0; i += 8) {
        int2 m[8];
        uint2 x[8];
#pragma unroll
        for (int k = 0; k < 8; k++) m[k] = __ldg(g_edge + i + k);
#pragma unroll
        for (int k = 0; k < 8; k++) x[k] = __ldg(srcH + (size_t)m[k].x * 16 + t);
#pragma unroll
        for (int k = 0; k < 8; k++) {
            u64 v = dup2(__int_as_float(m[k].y));
            float2 f01 = __half22float2(*reinterpret_cast<__half2*>(&x[k].x));
            float2 f23 = __half22float2(*reinterpret_cast<__half2*>(&x[k].y));
            a01 = fma2(v, pack2(f01.x, f01.y), a01);
            a23 = fma2(v, pack2(f23.x, f23.y), a23);
        }
    }
    for (; i < e0; i++) {
        int2 m = __ldg(g_edge + i);
        uint2 x = __ldg(srcH + (size_t)m.x * 16 + t);
        u64 v = dup2(__int_as_float(m.y));
        float2 f01 = __half22float2(*reinterpret_cast<__half2*>(&x.x));
        float2 f23 = __half22float2(*reinterpret_cast<__half2*>(&x.y));
        a01 = fma2(v, pack2(f01.x, f01.y), a01);
        a23 = fma2(v, pack2(f23.x, f23.y), a23);
    }
}

// ---------------------------------------------------------------------------
// Fused layer: persistent blocks, 64-row tiles, 4 rows x 4 cols per thread.
//   agg  = A @ fp16(src);  ego' = leaky((src+agg)@W1 + (src*agg)@W2)
//   non-last: dst = ego'; dstH = fp16(ego')
//   last:     out = (egoA + egoB + src + ego') * 0.25
// ---------------------------------------------------------------------------
__global__ void __launch_bounds__(256, 3)
fused_layer_kernel(const float4* __restrict__ src,
                   const uint2* __restrict__ srcH,
                   float4* __restrict__ dst,
                   uint2* __restrict__ dstH,
                   const float4* __restrict__ w1,
                   const float4* __restrict__ w2,
                   int last, float4* __restrict__ out) {
    extern __shared__ char smem_raw[];
    float4* ws1 = reinterpret_cast<float4*>(smem_raw);              // 16KB
    float4* ws2 = reinterpret_cast<float4*>(smem_raw + 16384);      // 16KB
    float*  ssh = reinterpret_cast<float*>(smem_raw + 32768);       // 16KB (ego+agg)
    float*  psh = reinterpret_cast<float*>(smem_raw + 49152);       // 16KB (ego*agg)

    for (int i = threadIdx.x; i < EMB * 16; i += 256) {
        ws1[i] = w1[i];
        ws2[i] = w2[i];
    }

    const int t  = threadIdx.x & 15;    // output cols 4t..4t+3
    const int rq = threadIdx.x >> 4;    // rows rq, rq+16, rq+32, rq+48 of tile

    const ulonglong2* srcu = reinterpret_cast<const ulonglong2*>(src);
    const ulonglong2* w1u  = reinterpret_cast<const ulonglong2*>(ws1);
    const ulonglong2* w2u  = reinterpret_cast<const ulonglong2*>(ws2);

    for (int tile = blockIdx.x; tile < NTILE64; tile += gridDim.x) {
        __syncthreads();   // smem reuse guard (also orders weight preload)

        const int base = tile * 64 + rq;

        // ---- Phase 1: gather 4 rows, stage s = ego+agg, p = ego*agg ----
#pragma unroll
        for (int j = 0; j < 4; j++) {
            int row = base + 16 * j;
            if (row >= N_NODES) continue;
            u64 a01 = 0, a23 = 0;
            gather_row(srcH, row, t, a01, a23);
            ulonglong2 e = srcu[(size_t)row * 16 + t];
            ulonglong2 s4, p4;
            s4.x = add2(e.x, a01); s4.y = add2(e.y, a23);
            p4.x = mul2(e.x, a01); p4.y = mul2(e.y, a23);
            int lr = rq + 16 * j;
            *reinterpret_cast<ulonglong2*>(ssh + lr * EMB + 4 * t) = s4;
            *reinterpret_cast<ulonglong2*>(psh + lr * EMB + 4 * t) = p4;
        }
        __syncthreads();

        // ---- Phase 2: GEMV, 4 rows x 4 cols per thread ----
        u64 o01[4] = {0, 0, 0, 0};
        u64 o23[4] = {0, 0, 0, 0};

#pragma unroll
        for (int i4 = 0; i4 < 16; i4++) {
            float sA[4][4], pA[4][4];
#pragma unroll
            for (int j = 0; j < 4; j++) {
                int lr = rq + 16 * j;
                ulonglong2 sv = *reinterpret_cast<const ulonglong2*>(ssh + lr * EMB + 4 * i4);
                ulonglong2 pv = *reinterpret_cast<const ulonglong2*>(psh + lr * EMB + 4 * i4);
                float2 s01 = unpack2(sv.x), s23 = unpack2(sv.y);
                float2 p01 = unpack2(pv.x), p23 = unpack2(pv.y);
                sA[j][0] = s01.x; sA[j][1] = s01.y; sA[j][2] = s23.x; sA[j][3] = s23.y;
                pA[j][0] = p01.x; pA[j][1] = p01.y; pA[j][2] = p23.x; pA[j][3] = p23.y;
            }
#pragma unroll
            for (int u = 0; u < 4; u++) {
                ulonglong2 wa = w1u[(i4 * 4 + u) * 16 + t];
                ulonglong2 wb = w2u[(i4 * 4 + u) * 16 + t];
#pragma unroll
                for (int j = 0; j < 4; j++) {
                    u64 sd = dup2(sA[j][u]);
                    u64 pd = dup2(pA[j][u]);
                    o01[j] = fma2(sd, wa.x, o01[j]);
                    o23[j] = fma2(sd, wa.y, o23[j]);
                    o01[j] = fma2(pd, wb.x, o01[j]);
                    o23[j] = fma2(pd, wb.y, o23[j]);
                }
            }
        }

        // ---- Epilogue: leaky_relu, write fp32 (+fp16 shadow) ----
#pragma unroll
        for (int j = 0; j < 4; j++) {
            int row = base + 16 * j;
            if (row >= N_NODES) continue;
            float2 A01 = unpack2(o01[j]), A23 = unpack2(o23[j]);
            A01.x = A01.x > 0.f ? A01.x : 0.01f * A01.x;
            A01.y = A01.y > 0.f ? A01.y : 0.01f * A01.y;
            A23.x = A23.x > 0.f ? A23.x : 0.01f * A23.x;
            A23.y = A23.y > 0.f ? A23.y : 0.01f * A23.y;
            u64 l01 = pack2(A01.x, A01.y);
            u64 l23 = pack2(A23.x, A23.y);
            size_t idx = (size_t)row * 16 + t;

            if (!last) {
                ulonglong2 o; o.x = l01; o.y = l23;
                reinterpret_cast<ulonglong2*>(dst)[idx] = o;
                dstH[idx] = f4_to_h4(A01.x, A01.y, A23.x, A23.y);
            } else {
                const ulonglong2* e0u = reinterpret_cast<const ulonglong2*>(g_egoA);
                const ulonglong2* e1u = reinterpret_cast<const ulonglong2*>(g_egoB);
                u64 q = dup2(0.25f);
                ulonglong2 v0 = e0u[idx], v1 = e1u[idx], v2 = srcu[idx];
                ulonglong2 o;
                o.x = mul2(add2(add2(v0.x, v1.x), add2(v2.x, l01)), q);
                o.y = mul2(add2(add2(v0.y, v1.y), add2(v2.y, l23)), q);
                reinterpret_cast<ulonglong2*>(out)[idx] = o;
            }
        }
    }
}

// ---------------------------------------------------------------------------
extern "C" void kernel_launch(void* const* d_in, const int* in_sizes, int n_in,
                              void* d_out, int out_size) {
    const float* user = (const float*)d_in[0];
    const float* item = (const float*)d_in[1];
    const float* w1   = (const float*)d_in[2];
    const float* w2   = (const float*)d_in[3];
    const float* vals = (const float*)d_in[4];
    const int*   rows = (const int*)d_in[5];
    const int*   cols = (const int*)d_in[6];
    int nnz = in_sizes[4];
    if (nnz > NNZ_MAX) nnz = NNZ_MAX;

    const int gv = (TOT4 + 255) / 256;
    const int ge = (nnz + 255) / 256;

    cudaFuncSetAttribute(fused_layer_kernel,
                         cudaFuncAttributeMaxDynamicSharedMemorySize, FUSED_SMEM);

    init_kernel<<<gv, 256>>>((const float4*)user, (const float4*)item);

    hist_kernel<<<ge, 256>>>(rows, nnz);
    scan1_kernel<<<NSCAN_BLK, 256>>>();
    scan2_kernel<<<1, 1024>>>();
    scan3_kernel<<<NSCAN_BLK, 256>>>(nnz);
    scatter_kernel<<<ge, 256>>>(rows, cols, vals, nnz);

    float4* egoA = nullptr;
    float4* egoB = nullptr;
    float4* egoC = nullptr;
    uint2*  h0 = nullptr;
    uint2*  h1 = nullptr;
    cudaGetSymbolAddress((void**)&egoA, g_egoA);
    cudaGetSymbolAddress((void**)&egoB, g_egoB);
    cudaGetSymbolAddress((void**)&egoC, g_egoC);
    cudaGetSymbolAddress((void**)&h0, g_h0);
    cudaGetSymbolAddress((void**)&h1, g_h1);

    const float4* w1v = (const float4*)w1;
    const float4* w2v = (const float4*)w2;

    // layer 0: A(h0) -> B(h1), layer 1: B(h1) -> C(h0), layer 2: C(h0) -> out
    fused_layer_kernel<<<FUSED_GRID, 256, FUSED_SMEM>>>(egoA, h0, egoB, h1,
                                                        w1v, w2v, 0, nullptr);
    fused_layer_kernel<<<FUSED_GRID, 256, FUSED_SMEM>>>(egoB, h1, egoC, h0,
                                                        w1v + 1024, w2v + 1024, 0, nullptr);
    fused_layer_kernel<<<FUSED_GRID, 256, FUSED_SMEM>>>(egoC, h0, nullptr, nullptr,
                                                        w1v + 2048, w2v + 2048, 1,
                                                        (float4*)d_out);
}